// round 8
// baseline (speedup 1.0000x reference)
#include <cuda_runtime.h>
#include <math.h>

// ---------------------------------------------------------------------------
// Problem constants
// ---------------------------------------------------------------------------
#define BATCH   2
#define SEQ     2048
#define DMODEL  1024
#define HEADS   16
#define DK      64
#define NTOK    (BATCH * SEQ)        // 4096

// ---------------------------------------------------------------------------
// Scratch (device globals — no allocation allowed)
// ---------------------------------------------------------------------------
__device__ float g_Q  [(size_t)NTOK * DMODEL];
__device__ float g_K  [(size_t)NTOK * DMODEL];
__device__ float g_V  [(size_t)NTOK * DMODEL];
__device__ float g_CTX[(size_t)NTOK * DMODEL];
__device__ float g_cos[SEQ * (DK / 2)];
__device__ float g_sin[SEQ * (DK / 2)];

// ---------------------------------------------------------------------------
// RoPE table: mimic reference fp32 rounding of the angle, accurate trig.
// ---------------------------------------------------------------------------
__global__ void rope_table_kernel(float* __restrict__ cosT, float* __restrict__ sinT)
{
    int idx = blockIdx.x * blockDim.x + threadIdx.x;
    if (idx >= SEQ * (DK / 2)) return;
    int s = idx >> 5;          // position
    int i = idx & 31;          // pair index
    double inv = pow(10000.0, -((double)(2 * i) / (double)DK));
    float  invf = (float)inv;                 // fp32 inv_freq (as reference)
    float  ang  = (float)s * invf;            // fp32 angle (as reference)
    cosT[idx] = (float)cos((double)ang);
    sinT[idx] = (float)sin((double)ang);
}

// ---------------------------------------------------------------------------
// SGEMM  C[M,N] = A[M,K] * B[N,K]^T   (both row-major, K contiguous)
// 128x128 tile, BK=16, 256 threads, 8x8 per thread.
// Optional fused interleaved-pair RoPE on the output (per head of 64 cols).
// ---------------------------------------------------------------------------
#define GM 128
#define GN 128
#define GK 16

template<bool ROPE>
__global__ __launch_bounds__(256)
void gemm_nt_kernel(const float* __restrict__ A, const float* __restrict__ Bw,
                    float* __restrict__ C, int M, int N, int K,
                    const float* __restrict__ cosT, const float* __restrict__ sinT)
{
    __shared__ float As[GK][GM];
    __shared__ float Bs[GK][GN];

    const int tid = threadIdx.x;
    const int tx  = tid & 15;
    const int ty  = tid >> 4;
    const int m0  = blockIdx.y * GM;
    const int n0  = blockIdx.x * GN;

    float acc[8][8];
#pragma unroll
    for (int i = 0; i < 8; ++i)
#pragma unroll
        for (int j = 0; j < 8; ++j) acc[i][j] = 0.f;

    // global-load mapping: 128 rows x 16 cols = 512 float4; 2 per thread
    const int lr = tid >> 2;            // 0..63
    const int lc = (tid & 3) * 4;       // 0,4,8,12

    const float* Ap = A  + (size_t)(m0 + lr) * K + lc;
    const float* Bp = Bw + (size_t)(n0 + lr) * K + lc;
    const size_t half = (size_t)64 * K;

    for (int k0 = 0; k0 < K; k0 += GK) {
        float4 a0 = *(const float4*)(Ap + k0);
        float4 a1 = *(const float4*)(Ap + k0 + half);
        float4 b0 = *(const float4*)(Bp + k0);
        float4 b1 = *(const float4*)(Bp + k0 + half);

        __syncthreads();
        As[lc + 0][lr]      = a0.x; As[lc + 1][lr]      = a0.y;
        As[lc + 2][lr]      = a0.z; As[lc + 3][lr]      = a0.w;
        As[lc + 0][lr + 64] = a1.x; As[lc + 1][lr + 64] = a1.y;
        As[lc + 2][lr + 64] = a1.z; As[lc + 3][lr + 64] = a1.w;
        Bs[lc + 0][lr]      = b0.x; Bs[lc + 1][lr]      = b0.y;
        Bs[lc + 2][lr]      = b0.z; Bs[lc + 3][lr]      = b0.w;
        Bs[lc + 0][lr + 64] = b1.x; Bs[lc + 1][lr + 64] = b1.y;
        Bs[lc + 2][lr + 64] = b1.z; Bs[lc + 3][lr + 64] = b1.w;
        __syncthreads();

#pragma unroll
        for (int k = 0; k < GK; ++k) {
            float4 ra0 = *(const float4*)&As[k][ty * 4];
            float4 ra1 = *(const float4*)&As[k][ty * 4 + 64];
            float4 rb0 = *(const float4*)&Bs[k][tx * 4];
            float4 rb1 = *(const float4*)&Bs[k][tx * 4 + 64];
            float av[8] = {ra0.x, ra0.y, ra0.z, ra0.w, ra1.x, ra1.y, ra1.z, ra1.w};
            float bv[8] = {rb0.x, rb0.y, rb0.z, rb0.w, rb1.x, rb1.y, rb1.z, rb1.w};
#pragma unroll
            for (int i = 0; i < 8; ++i)
#pragma unroll
                for (int j = 0; j < 8; ++j)
                    acc[i][j] = fmaf(av[i], bv[j], acc[i][j]);
        }
    }

    // epilogue
#pragma unroll
    for (int i = 0; i < 8; ++i) {
        const int r = ((i & 4) << 4) + ty * 4 + (i & 3);   // i<4: ty*4+i, else +64
        const int m = m0 + r;
#pragma unroll
        for (int cb = 0; cb < 2; ++cb) {
            const int n = n0 + cb * 64 + tx * 4;
            float4 o;
            o.x = acc[i][cb * 4 + 0];
            o.y = acc[i][cb * 4 + 1];
            o.z = acc[i][cb * 4 + 2];
            o.w = acc[i][cb * 4 + 3];
            if (ROPE) {
                const int pos = m & (SEQ - 1);
                const int i0  = (n & 63) >> 1;        // pair index for (x,y)
                const float c0 = cosT[pos * 32 + i0];
                const float s0 = sinT[pos * 32 + i0];
                const float c1 = cosT[pos * 32 + i0 + 1];
                const float s1 = sinT[pos * 32 + i0 + 1];
                float x = o.x, y = o.y, z = o.z, w = o.w;
                o.x = x * c0 - y * s0;
                o.y = y * c0 + x * s0;
                o.z = z * c1 - w * s1;
                o.w = w * c1 + z * s1;
            }
            *(float4*)(C + (size_t)m * N + n) = o;
        }
    }
}

// ---------------------------------------------------------------------------
// Flash attention (causal), fp32. 64x64 tiles, 256 threads, 4x4 per thread.
// Q/K/V/O are token-major [NTOK, DMODEL] with head h at columns h*64..h*64+63.
// ---------------------------------------------------------------------------
#define PADK 65
#define ATTN_SMEM_FLOATS (3 * 64 * PADK + 64 * 64)
#define ATTN_SMEM_BYTES  (ATTN_SMEM_FLOATS * 4)

__global__ __launch_bounds__(256)
void attn_kernel(const float* __restrict__ Q, const float* __restrict__ K,
                 const float* __restrict__ V, float* __restrict__ O)
{
    extern __shared__ float sm[];
    float* Qs = sm;                       // [64][65]
    float* Ks = sm + 64 * PADK;           // [64][65]
    float* Ps = sm + 2 * 64 * PADK;       // [64][65]
    float* Vs = sm + 3 * 64 * PADK;       // [64][64]

    const int tid = threadIdx.x;
    const int tx  = tid & 15;
    const int ty  = tid >> 4;
    const int qt  = blockIdx.x;           // q tile 0..31
    const int bh  = blockIdx.y;           // 0..31
    const int b   = bh >> 4;
    const int h   = bh & 15;
    const int q0  = qt * 64;

    const size_t base = ((size_t)b * SEQ) * DMODEL + (size_t)h * DK;
    const float* Qg = Q + base;
    const float* Kg = K + base;
    const float* Vg = V + base;
    float*       Og = O + base;

    // load Q tile, pre-scaled by 1/sqrt(Dk) = 0.125
#pragma unroll
    for (int it = 0; it < 4; ++it) {
        int f   = tid + it * 256;
        int row = f >> 4;
        int c4  = (f & 15) << 2;
        float4 v = *(const float4*)(Qg + (size_t)(q0 + row) * DMODEL + c4);
        float* dst = Qs + row * PADK + c4;
        dst[0] = v.x * 0.125f; dst[1] = v.y * 0.125f;
        dst[2] = v.z * 0.125f; dst[3] = v.w * 0.125f;
    }

    float m_[4], l_[4], acc[4][4];
#pragma unroll
    for (int i = 0; i < 4; ++i) {
        m_[i] = -1e30f; l_[i] = 0.f;
#pragma unroll
        for (int j = 0; j < 4; ++j) acc[i][j] = 0.f;
    }

    for (int j = 0; j <= qt; ++j) {
        const int kv0 = j * 64;
        __syncthreads();   // previous iteration's smem reads complete
#pragma unroll
        for (int it = 0; it < 4; ++it) {
            int f   = tid + it * 256;
            int row = f >> 4;
            int c4  = (f & 15) << 2;
            float4 kv = *(const float4*)(Kg + (size_t)(kv0 + row) * DMODEL + c4);
            float* kd = Ks + row * PADK + c4;
            kd[0] = kv.x; kd[1] = kv.y; kd[2] = kv.z; kd[3] = kv.w;
            float4 vv = *(const float4*)(Vg + (size_t)(kv0 + row) * DMODEL + c4);
            *(float4*)(Vs + row * 64 + c4) = vv;
        }
        __syncthreads();

        // scores S = (Q/8) K^T
        float s[4][4];
#pragma unroll
        for (int i = 0; i < 4; ++i)
#pragma unroll
            for (int jj = 0; jj < 4; ++jj) s[i][jj] = 0.f;

#pragma unroll 16
        for (int d = 0; d < DK; ++d) {
            float qv[4], kv_[4];
#pragma unroll
            for (int i = 0; i < 4; ++i)  qv[i]  = Qs[(ty * 4 + i) * PADK + d];
#pragma unroll
            for (int jj = 0; jj < 4; ++jj) kv_[jj] = Ks[(tx * 4 + jj) * PADK + d];
#pragma unroll
            for (int i = 0; i < 4; ++i)
#pragma unroll
                for (int jj = 0; jj < 4; ++jj)
                    s[i][jj] = fmaf(qv[i], kv_[jj], s[i][jj]);
        }

        // causal mask (only the diagonal tile can have masked entries)
        if (j == qt) {
#pragma unroll
            for (int i = 0; i < 4; ++i)
#pragma unroll
                for (int jj = 0; jj < 4; ++jj)
                    if (kv0 + tx * 4 + jj > q0 + ty * 4 + i) s[i][jj] = -1e30f;
        }

        // online softmax, per row
#pragma unroll
        for (int i = 0; i < 4; ++i) {
            float rm = fmaxf(fmaxf(s[i][0], s[i][1]), fmaxf(s[i][2], s[i][3]));
#pragma unroll
            for (int off = 1; off < 16; off <<= 1)
                rm = fmaxf(rm, __shfl_xor_sync(0xffffffffu, rm, off));
            float mn    = fmaxf(m_[i], rm);
            float alpha = __expf(m_[i] - mn);
            float rs = 0.f;
#pragma unroll
            for (int jj = 0; jj < 4; ++jj) {
                s[i][jj] = __expf(s[i][jj] - mn);
                rs += s[i][jj];
            }
#pragma unroll
            for (int off = 1; off < 16; off <<= 1)
                rs += __shfl_xor_sync(0xffffffffu, rs, off);
            l_[i] = l_[i] * alpha + rs;
            m_[i] = mn;
#pragma unroll
            for (int jj = 0; jj < 4; ++jj) acc[i][jj] *= alpha;
            // stage P
            float* pd = Ps + (ty * 4 + i) * PADK + tx * 4;
            pd[0] = s[i][0]; pd[1] = s[i][1]; pd[2] = s[i][2]; pd[3] = s[i][3];
        }
        __syncthreads();

        // O += P @ V
#pragma unroll 16
        for (int k = 0; k < 64; ++k) {
            float pv[4], vv[4];
#pragma unroll
            for (int i = 0; i < 4; ++i)  pv[i] = Ps[(ty * 4 + i) * PADK + k];
#pragma unroll
            for (int jj = 0; jj < 4; ++jj) vv[jj] = Vs[k * 64 + tx * 4 + jj];
#pragma unroll
            for (int i = 0; i < 4; ++i)
#pragma unroll
                for (int jj = 0; jj < 4; ++jj)
                    acc[i][jj] = fmaf(pv[i], vv[jj], acc[i][jj]);
        }
    }

    // epilogue: normalize and store
#pragma unroll
    for (int i = 0; i < 4; ++i) {
        float inv = 1.f / l_[i];
        float4 o;
        o.x = acc[i][0] * inv; o.y = acc[i][1] * inv;
        o.z = acc[i][2] * inv; o.w = acc[i][3] * inv;
        *(float4*)(Og + (size_t)(q0 + ty * 4 + i) * DMODEL + tx * 4) = o;
    }
}

// ---------------------------------------------------------------------------
// Launch
// ---------------------------------------------------------------------------
extern "C" void kernel_launch(void* const* d_in, const int* in_sizes, int n_in,
                              void* d_out, int out_size)
{
    const float* x  = (const float*)d_in[0];
    const float* wq = (const float*)d_in[1];
    const float* wk = (const float*)d_in[2];
    const float* wv = (const float*)d_in[3];
    const float* wo = (const float*)d_in[4];
    float* out = (float*)d_out;

    float *Qb, *Kb, *Vb, *Cb, *cT, *sT;
    cudaGetSymbolAddress((void**)&Qb, g_Q);
    cudaGetSymbolAddress((void**)&Kb, g_K);
    cudaGetSymbolAddress((void**)&Vb, g_V);
    cudaGetSymbolAddress((void**)&Cb, g_CTX);
    cudaGetSymbolAddress((void**)&cT, g_cos);
    cudaGetSymbolAddress((void**)&sT, g_sin);

    cudaFuncSetAttribute(attn_kernel,
                         cudaFuncAttributeMaxDynamicSharedMemorySize,
                         ATTN_SMEM_BYTES);

    rope_table_kernel<<<(SEQ * 32 + 255) / 256, 256>>>(cT, sT);

    dim3 gg(DMODEL / GN, NTOK / GM);   // (8, 32)
    gemm_nt_kernel<true ><<<gg, 256>>>(x,  wq, Qb, NTOK, DMODEL, DMODEL, cT, sT);
    gemm_nt_kernel<true ><<<gg, 256>>>(x,  wk, Kb, NTOK, DMODEL, DMODEL, cT, sT);
    gemm_nt_kernel<false><<<gg, 256>>>(x,  wv, Vb, NTOK, DMODEL, DMODEL, cT, sT);

    attn_kernel<<<dim3(SEQ / 64, BATCH * HEADS), 256, ATTN_SMEM_BYTES>>>(Qb, Kb, Vb, Cb);

    gemm_nt_kernel<false><<<gg, 256>>>(Cb, wo, out, NTOK, DMODEL, DMODEL, cT, sT);
}

// round 10
// speedup vs baseline: 1.6187x; 1.6187x over previous
#include <cuda_runtime.h>
#include <cuda_bf16.h>
#include <math.h>
#include <stdint.h>

// ---------------------------------------------------------------------------
// Problem constants
// ---------------------------------------------------------------------------
#define BATCH   2
#define SEQ     2048
#define DMODEL  1024
#define HEADS   16
#define DK      64
#define NTOK    (BATCH * SEQ)        // 4096

// ---------------------------------------------------------------------------
// Scratch (device globals — no allocation allowed)
// ---------------------------------------------------------------------------
__device__ __align__(256) float g_Q  [(size_t)NTOK * DMODEL];
__device__ __align__(256) float g_K  [(size_t)NTOK * DMODEL];
__device__ __align__(256) float g_V  [(size_t)NTOK * DMODEL];
__device__ __align__(256) float g_CTX[(size_t)NTOK * DMODEL];
__device__ __align__(256) float g_cos[SEQ * (DK / 2)];
__device__ __align__(256) float g_sin[SEQ * (DK / 2)];

// bf16 split operands
__device__ __align__(256) __nv_bfloat16 g_xhi[(size_t)NTOK * DMODEL];
__device__ __align__(256) __nv_bfloat16 g_xlo[(size_t)NTOK * DMODEL];
__device__ __align__(256) __nv_bfloat16 g_chi[(size_t)NTOK * DMODEL];
__device__ __align__(256) __nv_bfloat16 g_clo[(size_t)NTOK * DMODEL];
__device__ __align__(256) __nv_bfloat16 g_whi[4][(size_t)DMODEL * DMODEL];
__device__ __align__(256) __nv_bfloat16 g_wlo[4][(size_t)DMODEL * DMODEL];

// ---------------------------------------------------------------------------
// Generic-PTX helpers (all sm_80+/sm_75+; safe for compute_103 target)
// ---------------------------------------------------------------------------
__device__ __forceinline__ uint32_t smem_to_u32(const void* p) {
    uint32_t a;
    asm("{ .reg .u64 t; cvta.to.shared.u64 t, %1; cvt.u32.u64 %0, t; }" : "=r"(a) : "l"(p));
    return a;
}
__device__ __forceinline__ uint32_t swz128(uint32_t bo) { return bo ^ ((bo >> 3) & 0x70); }

__device__ __forceinline__ void cp16(uint32_t dst, const void* src) {
    asm volatile("cp.async.cg.shared.global [%0], [%1], 16;" :: "r"(dst), "l"(src) : "memory");
}
__device__ __forceinline__ void cp_commit() { asm volatile("cp.async.commit_group;" ::: "memory"); }
__device__ __forceinline__ void cp_wait1()  { asm volatile("cp.async.wait_group 1;"  ::: "memory"); }

__device__ __forceinline__ void ldsm4(uint32_t addr, uint32_t& r0, uint32_t& r1,
                                      uint32_t& r2, uint32_t& r3) {
    asm volatile("ldmatrix.sync.aligned.m8n8.x4.shared.b16 {%0,%1,%2,%3}, [%4];"
                 : "=r"(r0), "=r"(r1), "=r"(r2), "=r"(r3) : "r"(addr));
}
__device__ __forceinline__ void mma16816(float& c0, float& c1, float& c2, float& c3,
                                         uint32_t a0, uint32_t a1, uint32_t a2, uint32_t a3,
                                         uint32_t b0, uint32_t b1) {
    asm volatile("mma.sync.aligned.m16n8k16.row.col.f32.bf16.bf16.f32 "
                 "{%0,%1,%2,%3}, {%4,%5,%6,%7}, {%8,%9}, {%0,%1,%2,%3};"
                 : "+f"(c0), "+f"(c1), "+f"(c2), "+f"(c3)
                 : "r"(a0), "r"(a1), "r"(a2), "r"(a3), "r"(b0), "r"(b1));
}

// ---------------------------------------------------------------------------
// RoPE table: mimic reference fp32 rounding of the angle, accurate trig.
// ---------------------------------------------------------------------------
__global__ void rope_table_kernel(float* __restrict__ cosT, float* __restrict__ sinT)
{
    int idx = blockIdx.x * blockDim.x + threadIdx.x;
    if (idx >= SEQ * (DK / 2)) return;
    int s = idx >> 5;
    int i = idx & 31;
    double inv = pow(10000.0, -((double)(2 * i) / (double)DK));
    float  invf = (float)inv;
    float  ang  = (float)s * invf;
    cosT[idx] = (float)cos((double)ang);
    sinT[idx] = (float)sin((double)ang);
}

// ---------------------------------------------------------------------------
// fp32 -> bf16 hi/lo split
// ---------------------------------------------------------------------------
__global__ void split_bf16_kernel(const float* __restrict__ src,
                                  __nv_bfloat16* __restrict__ hi,
                                  __nv_bfloat16* __restrict__ lo, int n4)
{
    int i = blockIdx.x * blockDim.x + threadIdx.x;
    if (i >= n4) return;
    float4 a = ((const float4*)src)[i];
    __nv_bfloat16 h0 = __float2bfloat16_rn(a.x);
    __nv_bfloat16 h1 = __float2bfloat16_rn(a.y);
    __nv_bfloat16 h2 = __float2bfloat16_rn(a.z);
    __nv_bfloat16 h3 = __float2bfloat16_rn(a.w);
    __nv_bfloat16 l0 = __float2bfloat16_rn(a.x - __bfloat162float(h0));
    __nv_bfloat16 l1 = __float2bfloat16_rn(a.y - __bfloat162float(h1));
    __nv_bfloat16 l2 = __float2bfloat16_rn(a.z - __bfloat162float(h2));
    __nv_bfloat16 l3 = __float2bfloat16_rn(a.w - __bfloat162float(h3));
    __nv_bfloat162* hp = (__nv_bfloat162*)hi;
    __nv_bfloat162* lp = (__nv_bfloat162*)lo;
    hp[2 * i]     = __halves2bfloat162(h0, h1);
    hp[2 * i + 1] = __halves2bfloat162(h2, h3);
    lp[2 * i]     = __halves2bfloat162(l0, l1);
    lp[2 * i + 1] = __halves2bfloat162(l2, l3);
}

// ---------------------------------------------------------------------------
// mma.sync bf16-split GEMM:  C[M,N] = A[M,K] * B[N,K]^T  (hh + hl + lh)
// CTA 128x128, BK=64, SW128 smem (128B rows), 2-stage cp.async pipeline.
// 8 warps, each 64x32 warp tile = 4x4 m16n8 accum tiles.
// Optional fused interleaved-pair RoPE on output column pairs.
// ---------------------------------------------------------------------------
#define TM 128
#define TN 128
#define KC 64
#define NKC (DMODEL / KC)                 // 16
#define TILE_BYTES (TM * KC * 2)          // 16384 per operand array
#define OFF_AHI 0
#define OFF_ALO (1 * TILE_BYTES)
#define OFF_BHI (2 * TILE_BYTES)
#define OFF_BLO (3 * TILE_BYTES)
#define STG_BYTES (4 * TILE_BYTES)        // 65536 per stage
#define GEMM_SMEM (2 * STG_BYTES)         // 131072

__device__ __forceinline__ void stage_load(
    const __nv_bfloat16* __restrict__ Ahi, const __nv_bfloat16* __restrict__ Alo,
    const __nv_bfloat16* __restrict__ Bhi, const __nv_bfloat16* __restrict__ Blo,
    int m0, int n0, int k0, uint32_t sbase, int tid)
{
#pragma unroll
    for (int i = 0; i < 4; ++i) {
        int v  = tid + i * 256;          // 1024 16B-vectors per operand array
        int r  = v >> 3;                 // row 0..127
        int c8 = v & 7;                  // 16B chunk 0..7
        uint32_t sw = swz128((uint32_t)(r * 128 + c8 * 16));
        size_t goA = (size_t)(m0 + r) * DMODEL + k0 + c8 * 8;
        size_t goB = (size_t)(n0 + r) * DMODEL + k0 + c8 * 8;
        cp16(sbase + OFF_AHI + sw, Ahi + goA);
        cp16(sbase + OFF_ALO + sw, Alo + goA);
        cp16(sbase + OFF_BHI + sw, Bhi + goB);
        cp16(sbase + OFF_BLO + sw, Blo + goB);
    }
}

template<bool ROPE>
__global__ __launch_bounds__(256)
void gemm_mma_kernel(const __nv_bfloat16* __restrict__ Ahi, const __nv_bfloat16* __restrict__ Alo,
                     const __nv_bfloat16* __restrict__ Bhi, const __nv_bfloat16* __restrict__ Blo,
                     float* __restrict__ C,
                     const float* __restrict__ cosT, const float* __restrict__ sinT)
{
    extern __shared__ char sm[];
    const uint32_t sb = smem_to_u32(sm);
    const int tid = threadIdx.x;
    const int wid = tid >> 5;
    const int lid = tid & 31;
    const int wm  = wid & 1;             // 2 warps in M
    const int wn  = wid >> 1;            // 4 warps in N
    const int m0c = blockIdx.y * TM;
    const int n0c = blockIdx.x * TN;
    const int mw  = wm * 64;
    const int nw  = wn * 32;

    float acc[4][4][4] = {};

    stage_load(Ahi, Alo, Bhi, Blo, m0c, n0c, 0, sb, tid);
    cp_commit();

    // lane decompositions for ldmatrix addressing
    const int al  = lid & 15;            // A: row within m16
    const int ah  = lid >> 4;            // A: k-half (0/1) -> +16B
    const int bl7 = lid & 7;             // B: row within n8
    const int bk  = (lid >> 3) & 1;      // B: k-half
    const int bh8 = (lid >> 4) << 3;     // B: second n8 of the pair

    for (int kc = 0; kc < NKC; ++kc) {
        if (kc + 1 < NKC)
            stage_load(Ahi, Alo, Bhi, Blo, m0c, n0c, (kc + 1) * KC,
                       sb + ((kc + 1) & 1) * STG_BYTES, tid);
        cp_commit();
        cp_wait1();                       // stage kc resident
        __syncthreads();

        const uint32_t base = sb + (kc & 1) * STG_BYTES;
#pragma unroll
        for (int c = 0; c < 4; ++c) {     // 4 k16 chunks in KC=64
            uint32_t bh[4][2], bl[4][2];
#pragma unroll
            for (int p = 0; p < 2; ++p) { // n8-tile pairs {0,1},{2,3}
                int brow = nw + p * 16 + bl7 + bh8;
                uint32_t swo = swz128((uint32_t)(brow * 128 + c * 32 + bk * 16));
                uint32_t q0, q1, q2, q3;
                ldsm4(base + OFF_BHI + swo, q0, q1, q2, q3);
                bh[p*2][0] = q0; bh[p*2][1] = q1; bh[p*2+1][0] = q2; bh[p*2+1][1] = q3;
                ldsm4(base + OFF_BLO + swo, q0, q1, q2, q3);
                bl[p*2][0] = q0; bl[p*2][1] = q1; bl[p*2+1][0] = q2; bl[p*2+1][1] = q3;
            }
            uint32_t a[4][4];
#pragma unroll
            for (int mt = 0; mt < 4; ++mt) {
                int arow = mw + mt * 16 + al;
                uint32_t swo = swz128((uint32_t)(arow * 128 + c * 32 + ah * 16));
                ldsm4(base + OFF_AHI + swo, a[mt][0], a[mt][1], a[mt][2], a[mt][3]);
            }
            // hh + hl with a = A_hi
#pragma unroll
            for (int mt = 0; mt < 4; ++mt)
#pragma unroll
                for (int nt = 0; nt < 4; ++nt) {
                    mma16816(acc[mt][nt][0], acc[mt][nt][1], acc[mt][nt][2], acc[mt][nt][3],
                             a[mt][0], a[mt][1], a[mt][2], a[mt][3], bh[nt][0], bh[nt][1]);
                    mma16816(acc[mt][nt][0], acc[mt][nt][1], acc[mt][nt][2], acc[mt][nt][3],
                             a[mt][0], a[mt][1], a[mt][2], a[mt][3], bl[nt][0], bl[nt][1]);
                }
            // lh with a = A_lo (reuse regs)
#pragma unroll
            for (int mt = 0; mt < 4; ++mt) {
                int arow = mw + mt * 16 + al;
                uint32_t swo = swz128((uint32_t)(arow * 128 + c * 32 + ah * 16));
                ldsm4(base + OFF_ALO + swo, a[mt][0], a[mt][1], a[mt][2], a[mt][3]);
            }
#pragma unroll
            for (int mt = 0; mt < 4; ++mt)
#pragma unroll
                for (int nt = 0; nt < 4; ++nt)
                    mma16816(acc[mt][nt][0], acc[mt][nt][1], acc[mt][nt][2], acc[mt][nt][3],
                             a[mt][0], a[mt][1], a[mt][2], a[mt][3], bh[nt][0], bh[nt][1]);
        }
        __syncthreads();
    }

    // epilogue: C fragment (d0,d1)=(row g, cols 2t,2t+1), (d2,d3)=(row g+8, same)
    const int g   = lid >> 2;
    const int tig = lid & 3;
#pragma unroll
    for (int mt = 0; mt < 4; ++mt) {
        const int r0 = m0c + mw + mt * 16 + g;
        const int r1 = r0 + 8;
        const int pos0 = r0 & (SEQ - 1);
        const int pos1 = r1 & (SEQ - 1);
#pragma unroll
        for (int nt = 0; nt < 4; ++nt) {
            const int col = n0c + nw + nt * 8 + tig * 2;
            float d0 = acc[mt][nt][0], d1 = acc[mt][nt][1];
            float d2 = acc[mt][nt][2], d3 = acc[mt][nt][3];
            if (ROPE) {
                const int p = (col & 63) >> 1;
                float c0 = cosT[pos0 * 32 + p], s0 = sinT[pos0 * 32 + p];
                float c1 = cosT[pos1 * 32 + p], s1 = sinT[pos1 * 32 + p];
                float x = d0, y = d1;
                d0 = x * c0 - y * s0;  d1 = y * c0 + x * s0;
                x = d2; y = d3;
                d2 = x * c1 - y * s1;  d3 = y * c1 + x * s1;
            }
            *(float2*)(C + (size_t)r0 * DMODEL + col) = make_float2(d0, d1);
            *(float2*)(C + (size_t)r1 * DMODEL + col) = make_float2(d2, d3);
        }
    }
}

// ---------------------------------------------------------------------------
// Flash attention (causal), fp32 (unchanged — at fp32 roofline)
// ---------------------------------------------------------------------------
#define PADK 65
#define ATTN_SMEM_FLOATS (3 * 64 * PADK + 64 * 64)
#define ATTN_SMEM_BYTES  (ATTN_SMEM_FLOATS * 4)

__global__ __launch_bounds__(256)
void attn_kernel(const float* __restrict__ Q, const float* __restrict__ K,
                 const float* __restrict__ V, float* __restrict__ O)
{
    extern __shared__ float smf[];
    float* Qs = smf;
    float* Ks = smf + 64 * PADK;
    float* Ps = smf + 2 * 64 * PADK;
    float* Vs = smf + 3 * 64 * PADK;

    const int tid = threadIdx.x;
    const int tx  = tid & 15;
    const int ty  = tid >> 4;
    const int qt  = blockIdx.x;
    const int bh  = blockIdx.y;
    const int b   = bh >> 4;
    const int h   = bh & 15;
    const int q0  = qt * 64;

    const size_t base = ((size_t)b * SEQ) * DMODEL + (size_t)h * DK;
    const float* Qg = Q + base;
    const float* Kg = K + base;
    const float* Vg = V + base;
    float*       Og = O + base;

#pragma unroll
    for (int it = 0; it < 4; ++it) {
        int f   = tid + it * 256;
        int row = f >> 4;
        int c4  = (f & 15) << 2;
        float4 v = *(const float4*)(Qg + (size_t)(q0 + row) * DMODEL + c4);
        float* dst = Qs + row * PADK + c4;
        dst[0] = v.x * 0.125f; dst[1] = v.y * 0.125f;
        dst[2] = v.z * 0.125f; dst[3] = v.w * 0.125f;
    }

    float m_[4], l_[4], acc[4][4];
#pragma unroll
    for (int i = 0; i < 4; ++i) {
        m_[i] = -1e30f; l_[i] = 0.f;
#pragma unroll
        for (int j = 0; j < 4; ++j) acc[i][j] = 0.f;
    }

    for (int j = 0; j <= qt; ++j) {
        const int kv0 = j * 64;
        __syncthreads();
#pragma unroll
        for (int it = 0; it < 4; ++it) {
            int f   = tid + it * 256;
            int row = f >> 4;
            int c4  = (f & 15) << 2;
            float4 kv = *(const float4*)(Kg + (size_t)(kv0 + row) * DMODEL + c4);
            float* kd = Ks + row * PADK + c4;
            kd[0] = kv.x; kd[1] = kv.y; kd[2] = kv.z; kd[3] = kv.w;
            float4 vv = *(const float4*)(Vg + (size_t)(kv0 + row) * DMODEL + c4);
            *(float4*)(Vs + row * 64 + c4) = vv;
        }
        __syncthreads();

        float s[4][4];
#pragma unroll
        for (int i = 0; i < 4; ++i)
#pragma unroll
            for (int jj = 0; jj < 4; ++jj) s[i][jj] = 0.f;

#pragma unroll 16
        for (int d = 0; d < DK; ++d) {
            float qv[4], kv_[4];
#pragma unroll
            for (int i = 0; i < 4; ++i)  qv[i]  = Qs[(ty * 4 + i) * PADK + d];
#pragma unroll
            for (int jj = 0; jj < 4; ++jj) kv_[jj] = Ks[(tx * 4 + jj) * PADK + d];
#pragma unroll
            for (int i = 0; i < 4; ++i)
#pragma unroll
                for (int jj = 0; jj < 4; ++jj)
                    s[i][jj] = fmaf(qv[i], kv_[jj], s[i][jj]);
        }

        if (j == qt) {
#pragma unroll
            for (int i = 0; i < 4; ++i)
#pragma unroll
                for (int jj = 0; jj < 4; ++jj)
                    if (kv0 + tx * 4 + jj > q0 + ty * 4 + i) s[i][jj] = -1e30f;
        }

#pragma unroll
        for (int i = 0; i < 4; ++i) {
            float rm = fmaxf(fmaxf(s[i][0], s[i][1]), fmaxf(s[i][2], s[i][3]));
#pragma unroll
            for (int off = 1; off < 16; off <<= 1)
                rm = fmaxf(rm, __shfl_xor_sync(0xffffffffu, rm, off));
            float mn    = fmaxf(m_[i], rm);
            float alpha = __expf(m_[i] - mn);
            float rs = 0.f;
#pragma unroll
            for (int jj = 0; jj < 4; ++jj) {
                s[i][jj] = __expf(s[i][jj] - mn);
                rs += s[i][jj];
            }
#pragma unroll
            for (int off = 1; off < 16; off <<= 1)
                rs += __shfl_xor_sync(0xffffffffu, rs, off);
            l_[i] = l_[i] * alpha + rs;
            m_[i] = mn;
#pragma unroll
            for (int jj = 0; jj < 4; ++jj) acc[i][jj] *= alpha;
            float* pd = Ps + (ty * 4 + i) * PADK + tx * 4;
            pd[0] = s[i][0]; pd[1] = s[i][1]; pd[2] = s[i][2]; pd[3] = s[i][3];
        }
        __syncthreads();

#pragma unroll 16
        for (int k = 0; k < 64; ++k) {
            float pv[4], vv[4];
#pragma unroll
            for (int i = 0; i < 4; ++i)  pv[i] = Ps[(ty * 4 + i) * PADK + k];
#pragma unroll
            for (int jj = 0; jj < 4; ++jj) vv[jj] = Vs[k * 64 + tx * 4 + jj];
#pragma unroll
            for (int i = 0; i < 4; ++i)
#pragma unroll
                for (int jj = 0; jj < 4; ++jj)
                    acc[i][jj] = fmaf(pv[i], vv[jj], acc[i][jj]);
        }
    }

#pragma unroll
    for (int i = 0; i < 4; ++i) {
        float inv = 1.f / l_[i];
        float4 o;
        o.x = acc[i][0] * inv; o.y = acc[i][1] * inv;
        o.z = acc[i][2] * inv; o.w = acc[i][3] * inv;
        *(float4*)(Og + (size_t)(q0 + ty * 4 + i) * DMODEL + tx * 4) = o;
    }
}

// ---------------------------------------------------------------------------
// Launch
// ---------------------------------------------------------------------------
extern "C" void kernel_launch(void* const* d_in, const int* in_sizes, int n_in,
                              void* d_out, int out_size)
{
    const float* x  = (const float*)d_in[0];
    const float* wq = (const float*)d_in[1];
    const float* wk = (const float*)d_in[2];
    const float* wv = (const float*)d_in[3];
    const float* wo = (const float*)d_in[4];
    float* out = (float*)d_out;

    float *Qb, *Kb, *Vb, *Cb, *cT, *sT;
    cudaGetSymbolAddress((void**)&Qb, g_Q);
    cudaGetSymbolAddress((void**)&Kb, g_K);
    cudaGetSymbolAddress((void**)&Vb, g_V);
    cudaGetSymbolAddress((void**)&Cb, g_CTX);
    cudaGetSymbolAddress((void**)&cT, g_cos);
    cudaGetSymbolAddress((void**)&sT, g_sin);

    __nv_bfloat16 *xhi, *xlo, *chi, *clo, *whi, *wlo;
    cudaGetSymbolAddress((void**)&xhi, g_xhi);
    cudaGetSymbolAddress((void**)&xlo, g_xlo);
    cudaGetSymbolAddress((void**)&chi, g_chi);
    cudaGetSymbolAddress((void**)&clo, g_clo);
    cudaGetSymbolAddress((void**)&whi, g_whi);
    cudaGetSymbolAddress((void**)&wlo, g_wlo);
    const size_t WN = (size_t)DMODEL * DMODEL;

    cudaFuncSetAttribute(attn_kernel,
                         cudaFuncAttributeMaxDynamicSharedMemorySize, ATTN_SMEM_BYTES);
    cudaFuncSetAttribute(gemm_mma_kernel<true>,
                         cudaFuncAttributeMaxDynamicSharedMemorySize, GEMM_SMEM);
    cudaFuncSetAttribute(gemm_mma_kernel<false>,
                         cudaFuncAttributeMaxDynamicSharedMemorySize, GEMM_SMEM);

    rope_table_kernel<<<(SEQ * 32 + 255) / 256, 256>>>(cT, sT);

    const int xN4 = NTOK * DMODEL / 4;
    const int wN4 = DMODEL * DMODEL / 4;
    split_bf16_kernel<<<(xN4 + 255) / 256, 256>>>(x,  xhi, xlo, xN4);
    split_bf16_kernel<<<(wN4 + 255) / 256, 256>>>(wq, whi + 0 * WN, wlo + 0 * WN, wN4);
    split_bf16_kernel<<<(wN4 + 255) / 256, 256>>>(wk, whi + 1 * WN, wlo + 1 * WN, wN4);
    split_bf16_kernel<<<(wN4 + 255) / 256, 256>>>(wv, whi + 2 * WN, wlo + 2 * WN, wN4);
    split_bf16_kernel<<<(wN4 + 255) / 256, 256>>>(wo, whi + 3 * WN, wlo + 3 * WN, wN4);

    dim3 gg(DMODEL / TN, NTOK / TM);   // (8, 32)
    gemm_mma_kernel<true ><<<gg, 256, GEMM_SMEM>>>(xhi, xlo, whi + 0 * WN, wlo + 0 * WN, Qb, cT, sT);
    gemm_mma_kernel<true ><<<gg, 256, GEMM_SMEM>>>(xhi, xlo, whi + 1 * WN, wlo + 1 * WN, Kb, cT, sT);
    gemm_mma_kernel<false><<<gg, 256, GEMM_SMEM>>>(xhi, xlo, whi + 2 * WN, wlo + 2 * WN, Vb, cT, sT);

    attn_kernel<<<dim3(SEQ / 64, BATCH * HEADS), 256, ATTN_SMEM_BYTES>>>(Qb, Kb, Vb, Cb);

    split_bf16_kernel<<<(xN4 + 255) / 256, 256>>>(Cb, chi, clo, xN4);
    gemm_mma_kernel<false><<<gg, 256, GEMM_SMEM>>>(chi, clo, whi + 3 * WN, wlo + 3 * WN, out, cT, sT);
}